// round 9
// baseline (speedup 1.0000x reference)
#include <cuda_runtime.h>
#include <cstdint>

#define LSEQ 96
#define DM 32
#define NNODES 2000

// 12.3 MB repacked complex frequency weights: [n][j4(12)][lane(32)][4 floats]
// lane = h*8+o ; j = e*6 + m*2 + which (0:W1,1:W2); float slot (j>>2)*128 + lane*4 + (j&3)
__device__ float g_Wc[(size_t)NNODES * 1536];

// ---------------- compile-time trig (constexpr Taylor, exact to ~1e-12) ----------------
__host__ __device__ constexpr double KPI = 3.14159265358979323846;
__host__ __device__ constexpr double tsin_(double x){ double x2=x*x;
  return x*(1 - x2/6*(1 - x2/20*(1 - x2/42*(1 - x2/72*(1 - x2/110*(1 - x2/156*(1 - x2/210)))))));
}
__host__ __device__ constexpr double tcos_(double x){ double x2=x*x;
  return 1 - x2/2*(1 - x2/12*(1 - x2/30*(1 - x2/56*(1 - x2/90*(1 - x2/132*(1 - x2/182))))));
}
__host__ __device__ constexpr double cs96(int k){ k=((k%96)+96)%96; int q=k/24, r=k%24; double x=r*(KPI/48);
  double c=tcos_(x), s=tsin_(x);
  return q==0? c : (q==1? -s : (q==2? -c : s)); }
__host__ __device__ constexpr double sn96(int k){ k=((k%96)+96)%96; int q=k/24, r=k%24; double x=r*(KPI/48);
  double c=tcos_(x), s=tsin_(x);
  return q==0? s : (q==1? c : (q==2? -s : -c)); }

// G_m(t): inverse-mode basis with edge-replicated moving-average detrend folded in.
__host__ __device__ constexpr double Gre_(int f, int t){
  int lo = (t-12 < 0) ? 0 : t-12;
  int hi = (t+12 > 95) ? 95 : t+12;
  double s = 0;
  for (int j = lo; j <= hi; ++j) s += cs96(f*j);
  if (t < 12)  s += (double)(12 - t) * cs96(0);
  if (t > 83)  s += (double)(t - 83) * cs96(f*95);
  return cs96(f*t) - s/25.0;
}
__host__ __device__ constexpr double Gim_(int f, int t){
  int lo = (t-12 < 0) ? 0 : t-12;
  int hi = (t+12 > 95) ? 95 : t+12;
  double s = 0;
  for (int j = lo; j <= hi; ++j) s += sn96(f*j);
  if (t < 12)  s += (double)(12 - t) * sn96(0);
  if (t > 83)  s += (double)(t - 83) * sn96(f*95);
  return sn96(f*t) - s/25.0;
}

// ---------------- W repack kernel: float4 in, smem scatter, float4 out ----------------
__global__ __launch_bounds__(384)
void repack_kernel(const float* __restrict__ W1, const float* __restrict__ W2)
{
    __shared__ float s[1536];
    const int n = blockIdx.x;
    const int t = threadIdx.x;                          // 0..383
    const int which = (t >= 192);
    const int ti = which ? t - 192 : t;                 // 0..191 float4 index
    const float* base = which ? W2 : W1;
    float4 v = ((const float4*)(base + (size_t)n * 768))[ti];
    float vv[4] = {v.x, v.y, v.z, v.w};
    #pragma unroll
    for (int k = 0; k < 4; ++k) {
        int src = ti * 4 + k;
        int h = src / 192, r = src % 192;
        int e = r / 24,   rr = r % 24;
        int o = rr / 3,   m  = rr % 3;
        int lane = h * 8 + o;
        int j = e * 6 + m * 2 + which;
        s[(j >> 2) * 128 + lane * 4 + (j & 3)] = vv[k];
    }
    __syncthreads();
    float4 ov = *(const float4*)&s[t * 4];
    ((float4*)g_Wc)[(size_t)n * 384 + t] = ov;          // coalesced STG.128
}

// ---------------- TMA bulk + mbarrier + f32x2 helpers ----------------
__device__ __forceinline__ void mbar_init(unsigned int mbar, unsigned int cnt){
    asm volatile("mbarrier.init.shared.b64 [%0], %1;" :: "r"(mbar), "r"(cnt) : "memory");
}
__device__ __forceinline__ void mbar_expect_tx(unsigned int mbar, unsigned int bytes){
    asm volatile("mbarrier.arrive.expect_tx.shared.b64 _, [%0], %1;" :: "r"(mbar), "r"(bytes) : "memory");
}
__device__ __forceinline__ void bulk_g2s(unsigned int sdst, const void* gsrc, unsigned int bytes, unsigned int mbar){
    asm volatile("cp.async.bulk.shared::cta.global.mbarrier::complete_tx::bytes [%0], [%1], %2, [%3];"
                 :: "r"(sdst), "l"(gsrc), "r"(bytes), "r"(mbar) : "memory");
}
__device__ __forceinline__ void bulk_s2g(void* gdst, unsigned int ssrc, unsigned int bytes){
    asm volatile("cp.async.bulk.global.shared::cta.bulk_group [%0], [%1], %2;"
                 :: "l"(gdst), "r"(ssrc), "r"(bytes) : "memory");
}
__device__ __forceinline__ void mbar_wait(unsigned int mbar, unsigned int parity){
    asm volatile(
        "{\n\t.reg .pred P1;\n\t"
        "WAIT_%=:\n\t"
        "mbarrier.try_wait.parity.acquire.cta.shared::cta.b64 P1, [%0], %1, 0x989680;\n\t"
        "@P1 bra.uni DONE_%=;\n\t"
        "bra.uni WAIT_%=;\n\t"
        "DONE_%=:\n\t}"
        :: "r"(mbar), "r"(parity) : "memory");
}
__device__ __forceinline__ unsigned long long pack2(float lo, float hi){
    unsigned long long r;
    asm("mov.b64 %0, {%1, %2};" : "=l"(r) : "f"(lo), "f"(hi));
    return r;
}
__device__ __forceinline__ void unpack2(unsigned long long v, float& lo, float& hi){
    asm("mov.b64 {%0, %1}, %2;" : "=f"(lo), "=f"(hi) : "l"(v));
}
__device__ __forceinline__ void ffma2(unsigned long long& acc, unsigned long long a, unsigned long long b){
    asm("fma.rn.f32x2 %0, %1, %2, %0;" : "+l"(acc) : "l"(a), "l"(b));
}
__device__ __forceinline__ void fmul2(unsigned long long& a, unsigned long long b){
    asm("mul.rn.f32x2 %0, %0, %1;" : "+l"(a) : "l"(b));
}

// ---------------- Phase B: 3-mode DFT, paired symmetry, immediate trig ----------------
struct Acc6 { float ar0, ai0, ar1, ai1, ar2, ai2; };

template<int L> __device__ __forceinline__ void bpair(Acc6& a, const float* xp){
  float xl = xp[L*DM];
  float xh = xp[(96-L)*DM];
  float sum = xl + xh, dif = xl - xh;
  constexpr float c0=(float)cs96(1*L), s0=(float)sn96(1*L);
  constexpr float c1=(float)cs96(4*L), s1=(float)sn96(4*L);
  constexpr float c2=(float)cs96(5*L), s2=(float)sn96(5*L);
  a.ar0=fmaf(sum,c0,a.ar0); a.ai0=fmaf(dif,-s0,a.ai0);
  a.ar1=fmaf(sum,c1,a.ar1); a.ai1=fmaf(dif,-s1,a.ai1);
  a.ar2=fmaf(sum,c2,a.ar2); a.ai2=fmaf(dif,-s2,a.ai2);
}
template<int L> __device__ __forceinline__ void bpairs(Acc6& a, const float* xp){
  if constexpr (L <= 47){ bpair<L>(a, xp); bpairs<L+1>(a, xp); }
}

// ---------------- fused inverse-transform + detrend (F+G), in-place STS out ----------------
template<int T> __device__ __forceinline__ void fgstep(
    float* xpw, float ring[26], float& run, float x0, float& x95,
    float zr0, float zi0, float zr1, float zi1, float zr2, float zi2)
{
  float cur = ring[T % 26];
  constexpr float g0r=(float)Gre_(1,T), ng0i=-(float)Gim_(1,T);
  constexpr float g1r=(float)Gre_(4,T), ng1i=-(float)Gim_(4,T);
  constexpr float g2r=(float)Gre_(5,T), ng2i=-(float)Gim_(5,T);
  float v = fmaf(run, -(1.0f/25.0f), cur);     // base = x[t] - trend
  v = fmaf(zr0, g0r, v);  v = fmaf(zi0, ng0i, v);
  v = fmaf(zr1, g1r, v);  v = fmaf(zi1, ng1i, v);
  v = fmaf(zr2, g2r, v);  v = fmaf(zi2, ng2i, v);
  xpw[T*DM] = v;                                // STS, row T only read at steps <= T
  float subv = (T-12 >= 0) ? ring[(T+14) % 26] : x0;
  float addv;
  if constexpr (T+13 <= 95) addv = xpw[(T+13)*DM]; else addv = x95;
  if constexpr (T+13 == 95) x95 = addv;
  ring[(T+13) % 26] = addv;
  run += addv - subv;
}
template<int T> __device__ __forceinline__ void fgloop(
    float* xpw, float ring[26], float& run, float x0, float& x95,
    float zr0, float zi0, float zr1, float zi1, float zr2, float zi2)
{
  if constexpr (T < LSEQ){
    fgstep<T>(xpw, ring, run, x0, x95, zr0, zi0, zr1, zi1, zr2, zi2);
    fgloop<T+1>(xpw, ring, run, x0, x95, zr0, zi0, zr1, zi1, zr2, zi2);
  }
}

// One warp per (b,n) tile of [96 x 32], lane == channel d. 2 warps/block, grid 8000.
__global__ __launch_bounds__(64, 8)
void feldm_kernel(const float* __restrict__ x,
                  const float* __restrict__ Wq,
                  const float* __restrict__ Wo,
                  float* __restrict__ out)
{
    __shared__ __align__(16) float xbuf[2][LSEQ * DM];    // per-warp tile: x in, result out
    __shared__ float4 scr4[2][DM];                        // exchange: modes 0,1 (re,im pairs)
    __shared__ float2 scr2[2][DM];                        // exchange: mode 2
    __shared__ __align__(8) unsigned long long mbar[2];

    const int tid  = threadIdx.x;
    const int warp = tid >> 5;
    const int lane = tid & 31;

    const int unit = blockIdx.x * 2 + warp;     // b*2000 + n
    const int n    = unit % 2000;
    const float* __restrict__ xu = x   + (size_t)unit * (LSEQ * DM);
    float* __restrict__       ou = out + (size_t)unit * (LSEQ * DM);

    // ---- issue 12KB TMA bulk copy early ----
    unsigned int mb   = (unsigned int)__cvta_generic_to_shared(&mbar[warp]);
    unsigned int sbuf = (unsigned int)__cvta_generic_to_shared(&xbuf[warp][0]);
    if (lane == 0) {
        mbar_init(mb, 1);
        asm volatile("fence.proxy.async.shared::cta;" ::: "memory");
    }
    __syncwarp();
    if (lane == 0) {
        mbar_expect_tx(mb, LSEQ * DM * 4);
        bulk_g2s(sbuf, xu, LSEQ * DM * 4, mb);
    }

    // ---- overlap TMA latency: load per-node weights (coalesced) and Wq rows ----
    const int h = lane >> 3;
    float w[48];
    {
        const float4* wc = (const float4*)g_Wc + (size_t)n * 384 + lane;
        #pragma unroll
        for (int j4 = 0; j4 < 12; ++j4) {
            float4 v = wc[j4 * 32];
            w[4*j4] = v.x; w[4*j4+1] = v.y; w[4*j4+2] = v.z; w[4*j4+3] = v.w;
        }
    }
    float wrow[32];
    #pragma unroll
    for (int j = 0; j < 8; ++j) {
        float4 v = *(const float4*)&Wq[lane * 32 + 4 * j];
        wrow[4*j] = v.x; wrow[4*j+1] = v.y; wrow[4*j+2] = v.z; wrow[4*j+3] = v.w;
    }

    mbar_wait(mb, 0);
    __syncwarp();

    float* xpw = &xbuf[warp][lane];
    const float* xp = xpw;

    // ---- Phase B: 3-mode DFT, symmetric pairing (l=0,48 special; pairs 1..47) ----
    float xv0 = xp[0], xv48 = xp[48*DM];
    Acc6 a;
    a.ar0 = xv0 - xv48; a.ai0 = 0.f;    // f=1: cos(pi*48/48... ) -> cos(pi)= -1 at l=48
    a.ar1 = xv0 + xv48; a.ai1 = 0.f;    // f=4: cos(4pi) = +1
    a.ar2 = xv0 - xv48; a.ai2 = 0.f;    // f=5: cos(5pi) = -1
    bpairs<1>(a, xp);
    scr4[warp][lane] = make_float4(a.ar0, a.ai0, a.ar1, a.ai1);
    scr2[warp][lane] = make_float2(a.ar2, a.ai2);
    __syncwarp();

    // ---- Phase C (f32x2): Xq[c,m] = sum_d Wq[c,d] * Xx[d,m] ----
    unsigned long long acc0 = 0ull, acc1 = 0ull, acc2 = 0ull;   // (re,im) packed pairs
    #pragma unroll
    for (int d = 0; d < 32; ++d) {
        double2 t01 = *(const double2*)&scr4[warp][d];
        double  t2  = *(const double*) &scr2[warp][d];
        unsigned long long wp = pack2(wrow[d], wrow[d]);
        ffma2(acc0, wp, __double_as_longlong(t01.x));
        ffma2(acc1, wp, __double_as_longlong(t01.y));
        ffma2(acc2, wp, __double_as_longlong(t2));
    }
    __syncwarp();
    *(unsigned long long*)&scr4[warp][lane].x = acc0;
    *(unsigned long long*)&scr4[warp][lane].z = acc1;
    *(unsigned long long*)&scr2[warp][lane]   = acc2;
    __syncwarp();

    // ---- Phase D: per-head complex 8x8 mix (weights in regs) ----
    float or0=0.f,oi0=0.f,or1=0.f,oi1=0.f,or2=0.f,oi2=0.f;
    #pragma unroll
    for (int e = 0; e < 8; ++e) {
        float4 t0 = scr4[warp][h * 8 + e];
        float2 t1 = scr2[warp][h * 8 + e];
        float a0 = w[6*e+0], b0 = w[6*e+1];
        float a1 = w[6*e+2], b1 = w[6*e+3];
        float a2 = w[6*e+4], b2 = w[6*e+5];
        or0 += t0.x*a0 - t0.y*b0;  oi0 += t0.x*b0 + t0.y*a0;
        or1 += t0.z*a1 - t0.w*b1;  oi1 += t0.z*b1 + t0.w*a1;
        or2 += t1.x*a2 - t1.y*b2;  oi2 += t1.x*b2 + t1.y*a2;
    }
    __syncwarp();
    scr4[warp][lane] = make_float4(or0, oi0, or1, oi1);
    scr2[warp][lane] = make_float2(or2, oi2);
    __syncwarp();

    // ---- Phase E (f32x2): Z[dout,m] = (2/96) * sum_c O[c,m] * Wo[dout,c] ----
    #pragma unroll
    for (int j = 0; j < 8; ++j) {
        float4 v = *(const float4*)&Wo[lane * 32 + 4 * j];
        wrow[4*j] = v.x; wrow[4*j+1] = v.y; wrow[4*j+2] = v.z; wrow[4*j+3] = v.w;
    }
    acc0 = 0ull; acc1 = 0ull; acc2 = 0ull;
    #pragma unroll
    for (int c = 0; c < 32; ++c) {
        double2 t01 = *(const double2*)&scr4[warp][c];
        double  t2  = *(const double*) &scr2[warp][c];
        unsigned long long wp = pack2(wrow[c], wrow[c]);
        ffma2(acc0, wp, __double_as_longlong(t01.x));
        ffma2(acc1, wp, __double_as_longlong(t01.y));
        ffma2(acc2, wp, __double_as_longlong(t2));
    }
    {
        const float inv = 2.0f / 96.0f;
        unsigned long long invp = pack2(inv, inv);
        fmul2(acc0, invp); fmul2(acc1, invp); fmul2(acc2, invp);
    }
    float zr0, zi0, zr1, zi1, zr2, zi2;
    unpack2(acc0, zr0, zi0);
    unpack2(acc1, zr1, zi1);
    unpack2(acc2, zr2, zi2);
    // bo cancels exactly in (xr - movavg(xr)): every window averages 25 values.

    // ---- F+G fused, results written in-place into xbuf via STS ----
    float ring[26];
    #pragma unroll
    for (int j = 0; j < 13; ++j) ring[j] = xp[j*DM];
    float x0 = ring[0], x95 = 0.f;
    float run = 12.0f * x0;
    #pragma unroll
    for (int j = 0; j < 13; ++j) run += ring[j];

    fgloop<0>(xpw, ring, run, x0, x95, zr0, zi0, zr1, zi1, zr2, zi2);

    // ---- bulk store 12KB result tile smem -> global ----
    __syncwarp();
    if (lane == 0) {
        asm volatile("fence.proxy.async.shared::cta;" ::: "memory");
        bulk_s2g(ou, sbuf, LSEQ * DM * 4);
        asm volatile("cp.async.bulk.commit_group;" ::: "memory");
        asm volatile("cp.async.bulk.wait_group 0;" ::: "memory");
    }
}

extern "C" void kernel_launch(void* const* d_in, const int* in_sizes, int n_in,
                              void* d_out, int out_size) {
    // metadata order: x, Wq, bq, Wk, bk, Wv, bv, Wo, bo, W1, W2
    const float* x  = (const float*)d_in[0];
    const float* Wq = (const float*)d_in[1];
    const float* Wo = (const float*)d_in[7];
    const float* W1 = (const float*)d_in[9];
    const float* W2 = (const float*)d_in[10];
    repack_kernel<<<NNODES, 384>>>(W1, W2);
    feldm_kernel<<<8000, 64>>>(x, Wq, Wo, (float*)d_out);
}

// round 10
// speedup vs baseline: 1.5655x; 1.5655x over previous
#include <cuda_runtime.h>
#include <cstdint>

#define LSEQ 96
#define DM 32
#define NNODES 2000

// 12.3 MB repacked complex frequency weights: [n][j4(12)][lane(32)][4 floats]
// lane = h*8+o ; j = e*6 + m*2 + which (0:W1,1:W2); float slot (j>>2)*128 + lane*4 + (j&3)
__device__ float g_Wc[(size_t)NNODES * 1536];

// ---------------- compile-time trig (constexpr Taylor, exact to ~1e-12) ----------------
__host__ __device__ constexpr double KPI = 3.14159265358979323846;
__host__ __device__ constexpr double tsin_(double x){ double x2=x*x;
  return x*(1 - x2/6*(1 - x2/20*(1 - x2/42*(1 - x2/72*(1 - x2/110*(1 - x2/156*(1 - x2/210)))))));
}
__host__ __device__ constexpr double tcos_(double x){ double x2=x*x;
  return 1 - x2/2*(1 - x2/12*(1 - x2/30*(1 - x2/56*(1 - x2/90*(1 - x2/132*(1 - x2/182))))));
}
__host__ __device__ constexpr double cs96(int k){ k=((k%96)+96)%96; int q=k/24, r=k%24; double x=r*(KPI/48);
  double c=tcos_(x), s=tsin_(x);
  return q==0? c : (q==1? -s : (q==2? -c : s)); }
__host__ __device__ constexpr double sn96(int k){ k=((k%96)+96)%96; int q=k/24, r=k%24; double x=r*(KPI/48);
  double c=tcos_(x), s=tsin_(x);
  return q==0? s : (q==1? c : (q==2? -s : -c)); }

// G_m(t): inverse-mode basis with edge-replicated moving-average detrend folded in.
__host__ __device__ constexpr double Gre_(int f, int t){
  int lo = (t-12 < 0) ? 0 : t-12;
  int hi = (t+12 > 95) ? 95 : t+12;
  double s = 0;
  for (int j = lo; j <= hi; ++j) s += cs96(f*j);
  if (t < 12)  s += (double)(12 - t) * cs96(0);
  if (t > 83)  s += (double)(t - 83) * cs96(f*95);
  return cs96(f*t) - s/25.0;
}
__host__ __device__ constexpr double Gim_(int f, int t){
  int lo = (t-12 < 0) ? 0 : t-12;
  int hi = (t+12 > 95) ? 95 : t+12;
  double s = 0;
  for (int j = lo; j <= hi; ++j) s += sn96(f*j);
  if (t < 12)  s += (double)(12 - t) * sn96(0);
  if (t > 83)  s += (double)(t - 83) * sn96(f*95);
  return sn96(f*t) - s/25.0;
}

// ---------------- W repack kernel (R8 version, 7.2us measured) ----------------
__global__ __launch_bounds__(384)
void repack_kernel(const float* __restrict__ W1, const float* __restrict__ W2)
{
    __shared__ float s[1536];
    const int n = blockIdx.x;
    const int t = threadIdx.x;                  // 0..383

    #pragma unroll
    for (int half = 0; half < 2; ++half) {
        int src = half * 384 + t;               // 0..767, coalesced
        float v1 = W1[(size_t)n * 768 + src];
        float v2 = W2[(size_t)n * 768 + src];
        int h = src / 192, r = src % 192;
        int e = r / 24,   rr = r % 24;
        int o = rr / 3,   m  = rr % 3;
        int lane = h * 8 + o;
        int j1 = e * 6 + m * 2;
        s[(j1 >> 2) * 128 + lane * 4 + (j1 & 3)] = v1;
        int j2 = j1 + 1;
        s[(j2 >> 2) * 128 + lane * 4 + (j2 & 3)] = v2;
    }
    __syncthreads();
    float4 v = *(const float4*)&s[t * 4];
    ((float4*)g_Wc)[(size_t)n * 384 + t] = v;   // coalesced STG.128
}

// ---------------- TMA bulk + mbarrier helpers ----------------
__device__ __forceinline__ void mbar_init(unsigned int mbar, unsigned int cnt){
    asm volatile("mbarrier.init.shared.b64 [%0], %1;" :: "r"(mbar), "r"(cnt) : "memory");
}
__device__ __forceinline__ void mbar_expect_tx(unsigned int mbar, unsigned int bytes){
    asm volatile("mbarrier.arrive.expect_tx.shared.b64 _, [%0], %1;" :: "r"(mbar), "r"(bytes) : "memory");
}
__device__ __forceinline__ void bulk_g2s(unsigned int sdst, const void* gsrc, unsigned int bytes, unsigned int mbar){
    asm volatile("cp.async.bulk.shared::cta.global.mbarrier::complete_tx::bytes [%0], [%1], %2, [%3];"
                 :: "r"(sdst), "l"(gsrc), "r"(bytes), "r"(mbar) : "memory");
}
__device__ __forceinline__ void mbar_wait(unsigned int mbar, unsigned int parity){
    asm volatile(
        "{\n\t.reg .pred P1;\n\t"
        "WAIT_%=:\n\t"
        "mbarrier.try_wait.parity.acquire.cta.shared::cta.b64 P1, [%0], %1, 0x989680;\n\t"
        "@P1 bra.uni DONE_%=;\n\t"
        "bra.uni WAIT_%=;\n\t"
        "DONE_%=:\n\t}"
        :: "r"(mbar), "r"(parity) : "memory");
}

// ---------------- Phase B: 3-mode DFT, symmetric pairing, immediate trig ----------------
struct Acc6 { float ar0, ai0, ar1, ai1, ar2, ai2; };

template<int L> __device__ __forceinline__ void bpair(Acc6& a, const float* xp){
  float xl = xp[L*DM];
  float xh = xp[(96-L)*DM];
  float sum = xl + xh, dif = xl - xh;
  constexpr float c0=(float)cs96(1*L), s0=(float)sn96(1*L);
  constexpr float c1=(float)cs96(4*L), s1=(float)sn96(4*L);
  constexpr float c2=(float)cs96(5*L), s2=(float)sn96(5*L);
  a.ar0=fmaf(sum,c0,a.ar0); a.ai0=fmaf(dif,-s0,a.ai0);
  a.ar1=fmaf(sum,c1,a.ar1); a.ai1=fmaf(dif,-s1,a.ai1);
  a.ar2=fmaf(sum,c2,a.ar2); a.ai2=fmaf(dif,-s2,a.ai2);
}
template<int L> __device__ __forceinline__ void bpairs(Acc6& a, const float* xp){
  if constexpr (L <= 47){ bpair<L>(a, xp); bpairs<L+1>(a, xp); }
}

// ---------------- fused inverse-transform + detrend (F+G), read-only smem, STG out ----------------
template<int T> __device__ __forceinline__ void fgstep(
    const float* xp, float* op, float ring[26], float& run, float x0, float& x95,
    float zr0, float zi0, float zr1, float zi1, float zr2, float zi2)
{
  float cur = ring[T % 26];
  constexpr float g0r=(float)Gre_(1,T), ng0i=-(float)Gim_(1,T);
  constexpr float g1r=(float)Gre_(4,T), ng1i=-(float)Gim_(4,T);
  constexpr float g2r=(float)Gre_(5,T), ng2i=-(float)Gim_(5,T);
  float v = fmaf(run, -(1.0f/25.0f), cur);     // base = x[t] - trend
  v = fmaf(zr0, g0r, v);  v = fmaf(zi0, ng0i, v);
  v = fmaf(zr1, g1r, v);  v = fmaf(zi1, ng1i, v);
  v = fmaf(zr2, g2r, v);  v = fmaf(zi2, ng2i, v);
  op[T*DM] = v;                                // coalesced STG, fire-and-forget
  float subv = (T-12 >= 0) ? ring[(T+14) % 26] : x0;
  float addv;
  if constexpr (T+13 <= 95) addv = xp[(T+13)*DM]; else addv = x95;
  if constexpr (T+13 == 95) x95 = addv;
  ring[(T+13) % 26] = addv;
  run += addv - subv;
}
template<int T> __device__ __forceinline__ void fgloop(
    const float* xp, float* op, float ring[26], float& run, float x0, float& x95,
    float zr0, float zi0, float zr1, float zi1, float zr2, float zi2)
{
  if constexpr (T < LSEQ){
    fgstep<T>(xp, op, ring, run, x0, x95, zr0, zi0, zr1, zi1, zr2, zi2);
    fgloop<T+1>(xp, op, ring, run, x0, x95, zr0, zi0, zr1, zi1, zr2, zi2);
  }
}

// One warp per (b,n) tile of [96 x 32], lane == channel d. 2 warps/block, grid 8000.
__global__ __launch_bounds__(64, 8)
void feldm_kernel(const float* __restrict__ x,
                  const float* __restrict__ Wq,
                  const float* __restrict__ Wo,
                  float* __restrict__ out)
{
    __shared__ __align__(16) float xbuf[2][LSEQ * DM];    // per-warp x tile (12KB each)
    __shared__ float4 scr4[2][DM];                        // exchange: modes 0,1
    __shared__ float2 scr2[2][DM];                        // exchange: mode 2
    __shared__ __align__(8) unsigned long long mbar[2];

    const int tid  = threadIdx.x;
    const int warp = tid >> 5;
    const int lane = tid & 31;

    const int unit = blockIdx.x * 2 + warp;     // b*2000 + n
    const int n    = unit % 2000;
    const float* __restrict__ xu = x   + (size_t)unit * (LSEQ * DM);
    float* __restrict__       op = out + (size_t)unit * (LSEQ * DM) + lane;

    // ---- issue 12KB TMA bulk copy early ----
    unsigned int mb = (unsigned int)__cvta_generic_to_shared(&mbar[warp]);
    if (lane == 0) {
        mbar_init(mb, 1);
        asm volatile("fence.proxy.async.shared::cta;" ::: "memory");
    }
    __syncwarp();
    if (lane == 0) {
        unsigned int sdst = (unsigned int)__cvta_generic_to_shared(&xbuf[warp][0]);
        mbar_expect_tx(mb, LSEQ * DM * 4);
        bulk_g2s(sdst, xu, LSEQ * DM * 4, mb);
    }

    // ---- overlap TMA latency: load per-node weights (coalesced) and Wq rows ----
    const int h = lane >> 3;
    float w[48];
    {
        const float4* wc = (const float4*)g_Wc + (size_t)n * 384 + lane;
        #pragma unroll
        for (int j4 = 0; j4 < 12; ++j4) {
            float4 v = wc[j4 * 32];
            w[4*j4] = v.x; w[4*j4+1] = v.y; w[4*j4+2] = v.z; w[4*j4+3] = v.w;
        }
    }
    float wrow[32];
    #pragma unroll
    for (int j = 0; j < 8; ++j) {
        float4 v = *(const float4*)&Wq[lane * 32 + 4 * j];
        wrow[4*j] = v.x; wrow[4*j+1] = v.y; wrow[4*j+2] = v.z; wrow[4*j+3] = v.w;
    }

    mbar_wait(mb, 0);
    __syncwarp();

    const float* xp = &xbuf[warp][lane];

    // ---- Phase B: 3-mode DFT, symmetric pairing (l=0 & l=48 special; pairs 1..47) ----
    // cs96 at l=48: f=1 -> -1, f=4 -> +1, f=5 -> -1 ; sin terms zero.
    float xv0 = xp[0], xv48 = xp[48*DM];
    Acc6 a;
    a.ar0 = xv0 - xv48; a.ai0 = 0.f;
    a.ar1 = xv0 + xv48; a.ai1 = 0.f;
    a.ar2 = xv0 - xv48; a.ai2 = 0.f;
    bpairs<1>(a, xp);
    scr4[warp][lane] = make_float4(a.ar0, a.ai0, a.ar1, a.ai1);
    scr2[warp][lane] = make_float2(a.ar2, a.ai2);
    __syncwarp();

    // ---- Phase C: Xq[c,m] = sum_d Wq[c,d] * Xx[d,m]  (bq feeds only mode 0 -> drops) ----
    float qr0=0.f,qi0=0.f,qr1=0.f,qi1=0.f,qr2=0.f,qi2=0.f;
    #pragma unroll
    for (int d = 0; d < 32; ++d) {
        float4 t0 = scr4[warp][d];
        float2 t1 = scr2[warp][d];
        float wv = wrow[d];
        qr0 = fmaf(wv, t0.x, qr0); qi0 = fmaf(wv, t0.y, qi0);
        qr1 = fmaf(wv, t0.z, qr1); qi1 = fmaf(wv, t0.w, qi1);
        qr2 = fmaf(wv, t1.x, qr2); qi2 = fmaf(wv, t1.y, qi2);
    }
    __syncwarp();
    scr4[warp][lane] = make_float4(qr0, qi0, qr1, qi1);
    scr2[warp][lane] = make_float2(qr2, qi2);
    __syncwarp();

    // ---- Phase D: per-head complex 8x8 mix (weights already in regs) ----
    float or0=0.f,oi0=0.f,or1=0.f,oi1=0.f,or2=0.f,oi2=0.f;
    #pragma unroll
    for (int e = 0; e < 8; ++e) {
        float4 t0 = scr4[warp][h * 8 + e];
        float2 t1 = scr2[warp][h * 8 + e];
        float a0 = w[6*e+0], b0 = w[6*e+1];
        float a1 = w[6*e+2], b1 = w[6*e+3];
        float a2 = w[6*e+4], b2 = w[6*e+5];
        or0 += t0.x*a0 - t0.y*b0;  oi0 += t0.x*b0 + t0.y*a0;
        or1 += t0.z*a1 - t0.w*b1;  oi1 += t0.z*b1 + t0.w*a1;
        or2 += t1.x*a2 - t1.y*b2;  oi2 += t1.x*b2 + t1.y*a2;
    }
    __syncwarp();
    scr4[warp][lane] = make_float4(or0, oi0, or1, oi1);
    scr2[warp][lane] = make_float2(or2, oi2);
    __syncwarp();

    // ---- Phase E: Z[dout,m] = (2/96) * sum_c O[c,m] * Wo[dout,c] ----
    #pragma unroll
    for (int j = 0; j < 8; ++j) {
        float4 v = *(const float4*)&Wo[lane * 32 + 4 * j];
        wrow[4*j] = v.x; wrow[4*j+1] = v.y; wrow[4*j+2] = v.z; wrow[4*j+3] = v.w;
    }
    float zr0=0.f,zi0=0.f,zr1=0.f,zi1=0.f,zr2=0.f,zi2=0.f;
    #pragma unroll
    for (int c = 0; c < 32; ++c) {
        float4 t0 = scr4[warp][c];
        float2 t1 = scr2[warp][c];
        float wv = wrow[c];
        zr0 = fmaf(wv, t0.x, zr0); zi0 = fmaf(wv, t0.y, zi0);
        zr1 = fmaf(wv, t0.z, zr1); zi1 = fmaf(wv, t0.w, zi1);
        zr2 = fmaf(wv, t1.x, zr2); zi2 = fmaf(wv, t1.y, zi2);
    }
    const float inv = 2.0f / 96.0f;
    zr0 *= inv; zi0 *= inv; zr1 *= inv; zi1 *= inv; zr2 *= inv; zi2 *= inv;
    // bo cancels exactly in (xr - movavg(xr)): every window averages 25 values.

    // ---- Phases F+G fused: out[t] = (x[t] - run/25) + Re(sum_m Z_m G_m(t)) ----
    float ring[26];
    #pragma unroll
    for (int j = 0; j < 13; ++j) ring[j] = xp[j*DM];
    float x0 = ring[0], x95 = 0.f;
    float run = 12.0f * x0;
    #pragma unroll
    for (int j = 0; j < 13; ++j) run += ring[j];

    fgloop<0>(xp, op, ring, run, x0, x95, zr0, zi0, zr1, zi1, zr2, zi2);
}

extern "C" void kernel_launch(void* const* d_in, const int* in_sizes, int n_in,
                              void* d_out, int out_size) {
    // metadata order: x, Wq, bq, Wk, bk, Wv, bv, Wo, bo, W1, W2
    const float* x  = (const float*)d_in[0];
    const float* Wq = (const float*)d_in[1];
    const float* Wo = (const float*)d_in[7];
    const float* W1 = (const float*)d_in[9];
    const float* W2 = (const float*)d_in[10];
    repack_kernel<<<NNODES, 384>>>(W1, W2);
    feldm_kernel<<<8000, 64>>>(x, Wq, Wo, (float*)d_out);
}